// round 1
// baseline (speedup 1.0000x reference)
#include <cuda_runtime.h>
#include <cstdint>

// Problem constants
#define BB   32
#define CC   16
#define NNODE 64
#define TLEN 4096
#define OUTD 16
#define TTILE 128

typedef unsigned long long u64;

// Scratch for the 16 precomputed 64x64 matrices M[o][j][i] = sum_n U[i,n]*theta[n,o]*U[j,n]
// (j-major so the main kernel reads ms[j][i] with i contiguous). 256 KB, L2-resident.
__device__ float g_M[OUTD * NNODE * NNODE];

// ---------------------------------------------------------------------------
// Kernel 1: precompute M. 65536 elements, 64-term sum each. Trivial cost.
// ---------------------------------------------------------------------------
__global__ void compute_M_kernel(const float* __restrict__ U,
                                 const float* __restrict__ theta) {
    int idx = blockIdx.x * 256 + threadIdx.x;   // 0..65535
    int o = idx >> 12;          // /4096
    int j = (idx >> 6) & 63;
    int i = idx & 63;
    float acc = 0.f;
#pragma unroll
    for (int n = 0; n < 64; ++n) {
        acc += U[i * 64 + n] * theta[n * 16 + o] * U[j * 64 + n];
    }
    g_M[idx] = acc;   // layout (o*64 + j)*64 + i
}

// ---------------------------------------------------------------------------
// Kernel 2: fused channel-sum + 16x (64x64 @ 64x128) GEMM with f32x2 FMAs.
// Grid: (T/128, B). Block: 256 threads. One CTA = one (b, 128-wide t tile).
// ---------------------------------------------------------------------------
__global__ void __launch_bounds__(256, 2)
spectral_main_kernel(const float* __restrict__ x, float* __restrict__ y) {
    // xs[n][128] as float4 rows: 64 * 32 float4 = 32 KB
    __shared__ float4 xs4[NNODE * 32];
    // ms[j][64] as float4 rows: 64 * 16 float4 = 16 KB
    __shared__ float4 ms4[NNODE * 16];

    const int tid = threadIdx.x;
    const int b   = blockIdx.y;
    const int t0  = blockIdx.x * TTILE;

    // ---- Phase 1: channel sum into smem: xs[n][tl] = sum_c x[b,c,n,t0+tl]
    // 2048 float4 elements, 8 per thread, 16 channels each (16 independent LDG.128 -> high MLP)
#pragma unroll
    for (int k = 0; k < 8; ++k) {
        int eid = tid + k * 256;          // 0..2047
        int n   = eid >> 5;               // 0..63
        int tc  = eid & 31;               // float4 column 0..31
        const float4* px =
            (const float4*)(x + ((size_t)b * CC * NNODE + n) * TLEN + t0) + tc;
        float4 s = make_float4(0.f, 0.f, 0.f, 0.f);
#pragma unroll
        for (int c = 0; c < CC; ++c) {
            float4 v = px[(size_t)c * (NNODE * (TLEN / 4))];
            s.x += v.x; s.y += v.y; s.z += v.z; s.w += v.w;
        }
        xs4[eid] = s;
    }

    // Thread tile mapping: 8 row-groups (rg) x 32 t-groups (tg).
    // Warp covers 4 rg x 8 tg so m-loads broadcast (8 lanes/addr) and
    // x-loads span one contiguous 128B window -> 1 wavefront each.
    const int w  = tid >> 5;
    const int l  = tid & 31;
    const int rg = ((w >> 2) << 2) + (l >> 3);   // 0..7  -> rows rg*8 .. rg*8+7
    const int tg = ((w & 3) << 3) + (l & 7);     // 0..31 -> t = tg*4 .. tg*4+3

    for (int o = 0; o < OUTD; ++o) {
        __syncthreads();   // xs ready (o==0) / previous reads of ms done (o>0)
        // stage M_o (4096 floats) into smem
        const float4* gm4 = (const float4*)g_M + o * 1024;
#pragma unroll
        for (int k = 0; k < 4; ++k) ms4[tid + k * 256] = gm4[tid + k * 256];
        __syncthreads();

        // 8 rows x 4 t as packed f32x2 accumulators
        u64 acc[8][2];
#pragma unroll
        for (int r = 0; r < 8; ++r) { acc[r][0] = 0ull; acc[r][1] = 0ull; }

#pragma unroll 8
        for (int j = 0; j < NNODE; ++j) {
            // x pair loads: xs[j][tg*4 .. tg*4+3] as one LDS.128
            ulonglong2 xv = *(const ulonglong2*)&xs4[j * 32 + tg];
            // m loads: ms[j][rg*8 .. rg*8+7] as two LDS.128 (broadcast within warp)
            float4 ma = ms4[j * 16 + rg * 2];
            float4 mb = ms4[j * 16 + rg * 2 + 1];
            float mv[8] = {ma.x, ma.y, ma.z, ma.w, mb.x, mb.y, mb.z, mb.w};
#pragma unroll
            for (int r = 0; r < 8; ++r) {
                u64 md;
                asm("mov.b64 %0, {%1, %1};" : "=l"(md) : "f"(mv[r]));
                asm("fma.rn.f32x2 %0, %1, %2, %0;"
                    : "+l"(acc[r][0]) : "l"(xv.x), "l"(md));
                asm("fma.rn.f32x2 %0, %1, %2, %0;"
                    : "+l"(acc[r][1]) : "l"(xv.y), "l"(md));
            }
        }

        // store: y[b,o,i,t0+tg*4 .. +3], one STG.128 per row, coalesced across tg
        float* ybase = y + (((size_t)b * OUTD + o) * NNODE) * TLEN + t0 + tg * 4;
#pragma unroll
        for (int r = 0; r < 8; ++r) {
            int i = rg * 8 + r;
            ulonglong2 v;
            v.x = acc[r][0];
            v.y = acc[r][1];
            *(ulonglong2*)(ybase + (size_t)i * TLEN) = v;
        }
    }
}

// ---------------------------------------------------------------------------
// kernel_launch: graph-capturable, allocation-free.
// Inputs (metadata order): x (B,C,N,T) f32, U (N,N) f32, theta (N,OUT) f32.
// Output: y (B,OUT,N,T) f32.
// ---------------------------------------------------------------------------
extern "C" void kernel_launch(void* const* d_in, const int* in_sizes, int n_in,
                              void* d_out, int out_size) {
    const float* x     = (const float*)d_in[0];
    const float* U     = (const float*)d_in[1];
    const float* theta = (const float*)d_in[2];
    float* y = (float*)d_out;

    compute_M_kernel<<<256, 256>>>(U, theta);
    spectral_main_kernel<<<dim3(TLEN / TTILE, BB), 256>>>(x, y);
}

// round 2
// speedup vs baseline: 1.0004x; 1.0004x over previous
#include <cuda_runtime.h>
#include <cstdint>

// Problem constants
#define BB   32
#define CC   16
#define NNODE 64
#define TLEN 4096
#define OUTD 16
#define TTILE 128

typedef unsigned long long u64;

// Scratch for the 16 precomputed 64x64 matrices M[o][j][i] = sum_n U[i,n]*theta[n,o]*U[j,n]
// (j-major so the main kernel reads ms[j][i] with i contiguous). 256 KB, L2-resident.
__device__ float g_M[OUTD * NNODE * NNODE];

// ---------------------------------------------------------------------------
// Kernel 1: precompute M. 65536 elements, 64-term sum each. Trivial cost.
// ---------------------------------------------------------------------------
__global__ void compute_M_kernel(const float* __restrict__ U,
                                 const float* __restrict__ theta) {
    int idx = blockIdx.x * 256 + threadIdx.x;   // 0..65535
    int o = idx >> 12;          // /4096
    int j = (idx >> 6) & 63;
    int i = idx & 63;
    float acc = 0.f;
#pragma unroll
    for (int n = 0; n < 64; ++n) {
        acc += U[i * 64 + n] * theta[n * 16 + o] * U[j * 64 + n];
    }
    g_M[idx] = acc;   // layout (o*64 + j)*64 + i
}

// ---------------------------------------------------------------------------
// Kernel 2: fused channel-sum + 16x (64x64 @ 64x128) GEMM with f32x2 FMAs.
// Grid: (T/128, B). Block: 256 threads. One CTA = one (b, 128-wide t tile).
// ---------------------------------------------------------------------------
__global__ void __launch_bounds__(256, 2)
spectral_main_kernel(const float* __restrict__ x, float* __restrict__ y) {
    // xs[n][128] as float4 rows: 64 * 32 float4 = 32 KB
    __shared__ float4 xs4[NNODE * 32];
    // ms[j][64] as float4 rows: 64 * 16 float4 = 16 KB
    __shared__ float4 ms4[NNODE * 16];

    const int tid = threadIdx.x;
    const int b   = blockIdx.y;
    const int t0  = blockIdx.x * TTILE;

    // ---- Phase 1: channel sum into smem: xs[n][tl] = sum_c x[b,c,n,t0+tl]
    // 2048 float4 elements, 8 per thread, 16 channels each (16 independent LDG.128 -> high MLP)
#pragma unroll
    for (int k = 0; k < 8; ++k) {
        int eid = tid + k * 256;          // 0..2047
        int n   = eid >> 5;               // 0..63
        int tc  = eid & 31;               // float4 column 0..31
        const float4* px =
            (const float4*)(x + ((size_t)b * CC * NNODE + n) * TLEN + t0) + tc;
        float4 s = make_float4(0.f, 0.f, 0.f, 0.f);
#pragma unroll
        for (int c = 0; c < CC; ++c) {
            float4 v = px[(size_t)c * (NNODE * (TLEN / 4))];
            s.x += v.x; s.y += v.y; s.z += v.z; s.w += v.w;
        }
        xs4[eid] = s;
    }

    // Thread tile mapping: 8 row-groups (rg) x 32 t-groups (tg).
    // Warp covers 4 rg x 8 tg so m-loads broadcast (8 lanes/addr) and
    // x-loads span one contiguous 128B window -> 1 wavefront each.
    const int w  = tid >> 5;
    const int l  = tid & 31;
    const int rg = ((w >> 2) << 2) + (l >> 3);   // 0..7  -> rows rg*8 .. rg*8+7
    const int tg = ((w & 3) << 3) + (l & 7);     // 0..31 -> t = tg*4 .. tg*4+3

    for (int o = 0; o < OUTD; ++o) {
        __syncthreads();   // xs ready (o==0) / previous reads of ms done (o>0)
        // stage M_o (4096 floats) into smem
        const float4* gm4 = (const float4*)g_M + o * 1024;
#pragma unroll
        for (int k = 0; k < 4; ++k) ms4[tid + k * 256] = gm4[tid + k * 256];
        __syncthreads();

        // 8 rows x 4 t as packed f32x2 accumulators
        u64 acc[8][2];
#pragma unroll
        for (int r = 0; r < 8; ++r) { acc[r][0] = 0ull; acc[r][1] = 0ull; }

#pragma unroll 8
        for (int j = 0; j < NNODE; ++j) {
            // x pair loads: xs[j][tg*4 .. tg*4+3] as one LDS.128
            ulonglong2 xv = *(const ulonglong2*)&xs4[j * 32 + tg];
            // m loads: ms[j][rg*8 .. rg*8+7] as two LDS.128 (broadcast within warp)
            float4 ma = ms4[j * 16 + rg * 2];
            float4 mb = ms4[j * 16 + rg * 2 + 1];
            float mv[8] = {ma.x, ma.y, ma.z, ma.w, mb.x, mb.y, mb.z, mb.w};
#pragma unroll
            for (int r = 0; r < 8; ++r) {
                u64 md;
                asm("mov.b64 %0, {%1, %1};" : "=l"(md) : "f"(mv[r]));
                asm("fma.rn.f32x2 %0, %1, %2, %0;"
                    : "+l"(acc[r][0]) : "l"(xv.x), "l"(md));
                asm("fma.rn.f32x2 %0, %1, %2, %0;"
                    : "+l"(acc[r][1]) : "l"(xv.y), "l"(md));
            }
        }

        // store: y[b,o,i,t0+tg*4 .. +3], one STG.128 per row, coalesced across tg
        float* ybase = y + (((size_t)b * OUTD + o) * NNODE) * TLEN + t0 + tg * 4;
#pragma unroll
        for (int r = 0; r < 8; ++r) {
            int i = rg * 8 + r;
            ulonglong2 v;
            v.x = acc[r][0];
            v.y = acc[r][1];
            *(ulonglong2*)(ybase + (size_t)i * TLEN) = v;
        }
    }
}

// ---------------------------------------------------------------------------
// kernel_launch: graph-capturable, allocation-free.
// Inputs (metadata order): x (B,C,N,T) f32, U (N,N) f32, theta (N,OUT) f32.
// Output: y (B,OUT,N,T) f32.
// ---------------------------------------------------------------------------
extern "C" void kernel_launch(void* const* d_in, const int* in_sizes, int n_in,
                              void* d_out, int out_size) {
    const float* x     = (const float*)d_in[0];
    const float* U     = (const float*)d_in[1];
    const float* theta = (const float*)d_in[2];
    float* y = (float*)d_out;

    compute_M_kernel<<<256, 256>>>(U, theta);
    spectral_main_kernel<<<dim3(TLEN / TTILE, BB), 256>>>(x, y);
}